// round 2
// baseline (speedup 1.0000x reference)
#include <cuda_runtime.h>
#include <cstdint>

#define B 64
#define P 2048
#define G 512
#define TPB 128
#define NP 4

// Scratch (allocation-free rule: __device__ globals)
__device__ float           g_sbox[B * P * 4];   // score-sorted boxes (x1,y1,w,h)
__device__ int             g_scls[B * P];       // score-sorted classes
__device__ unsigned short  g_cand[B * P];       // bestGtIdx | (candidate<<15)
__device__ float           g_aps[B];

__device__ __forceinline__ unsigned int f2ord(float f) {
    unsigned int u = __float_as_uint(f);
    return (u & 0x80000000u) ? ~u : (u | 0x80000000u);
}

// ---------------------------------------------------------------------------
// Kernel 1: per-image stable sort by descending score (bitonic, 2048 elems).
// Key = (~ord(score) << 32) | index  -> ascending sort == (score desc, idx asc),
// matching JAX's stable argsort(-scores). Payload (orig index) in low bits.
// Gathers boxes/classes into sorted layout for coalesced downstream reads.
// ---------------------------------------------------------------------------
__global__ void sort_kernel(const float* __restrict__ pboxes,
                            const float* __restrict__ pscores,
                            const int*   __restrict__ pcls) {
    __shared__ unsigned long long key[P];
    const int b = blockIdx.x, tid = threadIdx.x;

    const float* sc = pscores + b * P;
    for (int i = tid; i < P; i += blockDim.x) {
        unsigned int u = ~f2ord(sc[i]);
        key[i] = ((unsigned long long)u << 32) | (unsigned int)i;
    }

    for (int k = 2; k <= P; k <<= 1) {
        for (int j = k >> 1; j > 0; j >>= 1) {
            __syncthreads();
            for (int i = tid; i < P; i += blockDim.x) {
                int ixj = i ^ j;
                if (ixj > i) {
                    unsigned long long a = key[i], c = key[ixj];
                    bool up = ((i & k) == 0);
                    if ((a > c) == up) { key[i] = c; key[ixj] = a; }
                }
            }
        }
    }
    __syncthreads();

    const float4* pb = (const float4*)(pboxes + (size_t)b * P * 4);
    for (int r = tid; r < P; r += blockDim.x) {
        int idx = (int)(key[r] & 0xFFFFFFFFu);
        ((float4*)g_sbox)[b * P + r] = pb[idx];
        g_scls[b * P + r] = pcls[b * P + idx];
    }
}

// ---------------------------------------------------------------------------
// Kernel 2 (hot): per sorted prediction, argmax-IoU over all 512 GTs.
// Division-free: best kept as (num, den); update test inter*bden > bnum*un,
// threshold test bnum > 0.5*bden (union always > 0). Strict-> == first-max,
// matching the reference argmax tie rule. GT geometry staged in shared; each
// thread owns NP=4 predictions to amortize the 5 LDS per GT.
// ---------------------------------------------------------------------------
__global__ void iou_kernel(const float* __restrict__ gboxes,
                           const int*   __restrict__ gcls) {
    __shared__ float sx1[G], sy1[G], sx2[G], sy2[G], sga[G];
    const int b = blockIdx.y, tid = threadIdx.x;

    const float4* gb = (const float4*)(gboxes + (size_t)b * G * 4);
    for (int g = tid; g < G; g += TPB) {
        float4 v = gb[g];
        float x2 = v.x + v.z, y2 = v.y + v.w;
        sx1[g] = v.x; sy1[g] = v.y; sx2[g] = x2; sy2[g] = y2;
        // reference computes area from (x1+w)-x1 after rounding:
        sga[g] = fabsf((x2 - v.x) * (y2 - v.y));
    }
    __syncthreads();

    const int base = b * P + blockIdx.x * (TPB * NP) + tid;

    float px1[NP], py1[NP], px2[NP], py2[NP], pa[NP], bnum[NP], bden[NP];
    int   bidx[NP];
#pragma unroll
    for (int q = 0; q < NP; q++) {
        float4 v = ((const float4*)g_sbox)[base + q * TPB];
        px1[q] = v.x; py1[q] = v.y;
        px2[q] = v.x + v.z; py2[q] = v.y + v.w;
        pa[q]  = fabsf((px2[q] - px1[q]) * (py2[q] - py1[q])) + 1e-9f;
        bnum[q] = 0.0f; bden[q] = 1.0f; bidx[q] = 0;
    }

#pragma unroll 4
    for (int g = 0; g < G; g++) {
        float gx1 = sx1[g], gy1 = sy1[g], gx2 = sx2[g], gy2 = sy2[g], ga = sga[g];
#pragma unroll
        for (int q = 0; q < NP; q++) {
            float dx = fminf(px2[q], gx2) - fmaxf(px1[q], gx1);
            float dy = fminf(py2[q], gy2) - fmaxf(py1[q], gy1);
            dx = fmaxf(dx, 0.0f); dy = fmaxf(dy, 0.0f);
            float inter = dx * dy;
            float un    = (pa[q] + ga) - inter;          // eps folded into pa; > 0
            bool  takes = inter * bden[q] > bnum[q] * un; // iou > best (strict)
            bidx[q] = takes ? g     : bidx[q];
            bnum[q] = takes ? inter : bnum[q];
            bden[q] = takes ? un    : bden[q];
        }
    }

#pragma unroll
    for (int q = 0; q < NP; q++) {
        int rank = base + q * TPB;
        bool cand = (bnum[q] > 0.5f * bden[q]) &&
                    (g_scls[rank] == __ldg(&gcls[b * G + bidx[q]]));
        g_cand[rank] = (unsigned short)(bidx[q] | (cand ? 0x8000 : 0));
    }
}

// ---------------------------------------------------------------------------
// Kernel 3: per-image sequential greedy scan + incremental AP.
// AP = sum over TPs of (1/G)*0.5*(p_prev + p_cur); precisions reconstructed
// from the running TP count, so FP steps need no bookkeeping.
// ---------------------------------------------------------------------------
__global__ void scan_kernel() {
    __shared__ unsigned short cand[P];
    const int b = blockIdx.x, tid = threadIdx.x;

    const uint4* src = (const uint4*)(g_cand + b * P);
    for (int i = tid; i < P * 2 / 16; i += blockDim.x)
        ((uint4*)cand)[i] = src[i];
    __syncthreads();

    if (tid == 0) {
        unsigned int used[G / 32];
#pragma unroll
        for (int i = 0; i < G / 32; i++) used[i] = 0;

        int tpc = 0;
        float ap = 0.0f;
        for (int i = 0; i < P; i++) {
            unsigned short v = cand[i];
            if (v & 0x8000u) {
                int gi = v & 0x1FF;
                unsigned int m = 1u << (gi & 31);
                unsigned int w = used[gi >> 5];
                if (!(w & m)) {
                    used[gi >> 5] = w | m;
                    float pprev = (i == 0) ? 1.0f : (float)tpc / (float)i;
                    tpc++;
                    float pcur = (float)tpc / (float)(i + 1);
                    ap += 0.5f * (pprev + pcur);
                }
            }
        }
        g_aps[b] = ap * (1.0f / (float)G);
    }
}

// ---------------------------------------------------------------------------
// Kernel 4: deterministic mean over 64 image APs -> d_out[0].
// ---------------------------------------------------------------------------
__global__ void reduce_kernel(float* __restrict__ out) {
    __shared__ float s[B];
    s[threadIdx.x] = g_aps[threadIdx.x];
    __syncthreads();
    if (threadIdx.x == 0) {
        float t = 0.0f;
        for (int i = 0; i < B; i++) t += s[i];
        out[0] = t * (1.0f / (float)B);
    }
}

extern "C" void kernel_launch(void* const* d_in, const int* in_sizes, int n_in,
                              void* d_out, int out_size) {
    const float* pred_boxes   = (const float*)d_in[0];
    const float* pred_scores  = (const float*)d_in[1];
    const int*   pred_classes = (const int*)  d_in[2];
    const float* gt_boxes     = (const float*)d_in[3];
    const int*   gt_classes   = (const int*)  d_in[4];

    sort_kernel<<<B, 1024>>>(pred_boxes, pred_scores, pred_classes);
    iou_kernel<<<dim3(P / (TPB * NP), B), TPB>>>(gt_boxes, gt_classes);
    scan_kernel<<<B, 256>>>();
    reduce_kernel<<<1, B>>>((float*)d_out);
}

// round 10
// speedup vs baseline: 1.4878x; 1.4878x over previous
#include <cuda_runtime.h>
#include <cstdint>

#define B 64
#define P 2048
#define G 512
#define TPB 128
#define NP 4

typedef unsigned long long u64;

// Scratch (allocation-free rule: __device__ globals; zero at module load)
__device__ u64   g_win[B * G];    // per-gt max candidate key (0 = unmatched)
__device__ float g_aps[B];
__device__ int   g_ctr;           // arrival counter for fused final mean

__device__ __forceinline__ unsigned int f2ord(float f) {
    unsigned int u = __float_as_uint(f);
    return (u & 0x80000000u) ? ~u : (u | 0x80000000u);
}
// key: larger == earlier rank (score desc, then index asc). Always > 0.
__device__ __forceinline__ u64 make_key(float score, int idx) {
    return ((u64)f2ord(score) << 32) | (unsigned int)(~idx);
}

// ---------------------------------------------------------------------------
// Kernel 1 (hot): per prediction, argmax-IoU over 512 GTs.
// Division-free best: (num, den); update inter*bden > bnum*un (union > 0),
// threshold bnum > 0.5*bden. Strict-> == first-max (reference argmax ties).
// Greedy matching collapses per-gt (used[g] written only by g's own TP, read
// only by g's candidates): TP of gt g = earliest-rank candidate = max key
// -> one deterministic atomicMax per candidate. No sort needed at all.
// GT corners packed as float4 in shared: 1 LDS.128 + 1 LDS per g (broadcast,
// conflict-free) instead of 5 scalar LDS.
// ---------------------------------------------------------------------------
__global__ void iou_kernel(const float* __restrict__ pboxes,
                           const float* __restrict__ pscores,
                           const int*   __restrict__ pcls,
                           const float* __restrict__ gboxes,
                           const int*   __restrict__ gcls) {
    __shared__ float4 sg[G];          // {x1, y1, x2, y2}
    __shared__ float  sga[G];         // gt area
    __shared__ int    sgc[G];         // gt class
    const int b = blockIdx.y, tid = threadIdx.x;

    const float4* gb = (const float4*)(gboxes + (size_t)b * G * 4);
    for (int g = tid; g < G; g += TPB) {
        float4 v = gb[g];
        float x2 = v.x + v.z, y2 = v.y + v.w;
        sg[g]  = make_float4(v.x, v.y, x2, y2);
        sga[g] = fabsf((x2 - v.x) * (y2 - v.y));   // area from rounded corners
        sgc[g] = __ldg(&gcls[b * G + g]);
    }
    __syncthreads();

    const int p0 = blockIdx.x * (TPB * NP) + tid;   // original pred index base

    float px1[NP], py1[NP], px2[NP], py2[NP], pa[NP], bnum[NP], bden[NP];
    int   bidx[NP];
#pragma unroll
    for (int q = 0; q < NP; q++) {
        float4 v = ((const float4*)(pboxes + (size_t)b * P * 4))[p0 + q * TPB];
        px1[q] = v.x; py1[q] = v.y;
        px2[q] = v.x + v.z; py2[q] = v.y + v.w;
        pa[q]  = fabsf((px2[q] - px1[q]) * (py2[q] - py1[q])) + 1e-9f;
        bnum[q] = 0.0f; bden[q] = 1.0f; bidx[q] = 0;
    }

#pragma unroll 4
    for (int g = 0; g < G; g++) {
        float4 gc = sg[g];
        float  ga = sga[g];
#pragma unroll
        for (int q = 0; q < NP; q++) {
            float dx = fminf(px2[q], gc.z) - fmaxf(px1[q], gc.x);
            float dy = fminf(py2[q], gc.w) - fmaxf(py1[q], gc.y);
            dx = fmaxf(dx, 0.0f); dy = fmaxf(dy, 0.0f);
            float inter = dx * dy;
            float un    = (pa[q] + ga) - inter;           // eps in pa; always > 0
            bool  takes = inter * bden[q] > bnum[q] * un; // iou > best (strict)
            bidx[q] = takes ? g     : bidx[q];
            bnum[q] = takes ? inter : bnum[q];
            bden[q] = takes ? un    : bden[q];
        }
    }

#pragma unroll
    for (int q = 0; q < NP; q++) {
        int pi = p0 + q * TPB;
        bool cand = (bnum[q] > 0.5f * bden[q]) &&
                    (__ldg(&pcls[b * P + pi]) == sgc[bidx[q]]);
        if (cand) {
            u64 key = make_key(__ldg(&pscores[b * P + pi]), pi);
            atomicMax(&g_win[b * G + bidx[q]], key);
        }
    }
}

// ---------------------------------------------------------------------------
// Kernel 2: per-image AP from winner keys + fused final mean.
// Winner rank r = #{pred keys > winner key} (keys unique -> exact stable
// rank). TP index j = #{other gt winner keys > mine} (ranks unique across
// gts). FP trapezoid terms are 0. Resets this image's g_win slice for the
// next graph replay; last block performs the deterministic 64-way mean.
// ---------------------------------------------------------------------------
__global__ void ap_kernel(const float* __restrict__ pscores,
                          float* __restrict__ out) {
    __shared__ u64   sk[P];      // all P prediction keys of this image
    __shared__ u64   wk[G];      // per-gt winner keys
    __shared__ float part[256];
    __shared__ bool  last;
    const int b = blockIdx.x, tid = threadIdx.x;   // 256 threads

#pragma unroll
    for (int q = 0; q < P / 256; q++) {
        int i = tid + q * 256;
        sk[i] = make_key(__ldg(&pscores[b * P + i]), i);
    }
#pragma unroll
    for (int q = 0; q < G / 256; q++) {
        int g = tid + q * 256;
        wk[g] = g_win[b * G + g];
    }
    __syncthreads();

    // reset for next replay (all reads of g_win for this image are done)
#pragma unroll
    for (int q = 0; q < G / 256; q++) g_win[b * G + tid + q * 256] = 0ull;

    float s = 0.0f;
#pragma unroll
    for (int q = 0; q < G / 256; q++) {
        u64 w = wk[tid + q * 256];
        if (w != 0ull) {
            int r = 0;
#pragma unroll 8
            for (int i = 0; i < P; i++) r += (sk[i] > w);
            int j = 0;
#pragma unroll 8
            for (int g2 = 0; g2 < G; g2++) j += (wk[g2] > w);
            float pprev = (r == 0) ? 1.0f : __fdividef((float)j, (float)r);
            float pcur  = __fdividef((float)(j + 1), (float)(r + 1));
            s += 0.5f * (pprev + pcur);
        }
    }
    part[tid] = s;
    __syncthreads();
    for (int off = 128; off > 0; off >>= 1) {
        if (tid < off) part[tid] += part[tid + off];
        __syncthreads();
    }
    if (tid == 0) g_aps[b] = part[0] * (1.0f / (float)G);

    // fused deterministic mean: last block to arrive does the 64-way sum
    __threadfence();
    if (tid == 0) last = (atomicAdd(&g_ctr, 1) == B - 1);
    __syncthreads();
    if (last && tid == 0) {
        float t = 0.0f;
        for (int i = 0; i < B; i++) t += g_aps[i];
        out[0] = t * (1.0f / (float)B);
        g_ctr = 0;                                  // reset for next replay
    }
}

extern "C" void kernel_launch(void* const* d_in, const int* in_sizes, int n_in,
                              void* d_out, int out_size) {
    const float* pred_boxes   = (const float*)d_in[0];
    const float* pred_scores  = (const float*)d_in[1];
    const int*   pred_classes = (const int*)  d_in[2];
    const float* gt_boxes     = (const float*)d_in[3];
    const int*   gt_classes   = (const int*)  d_in[4];

    iou_kernel<<<dim3(P / (TPB * NP), B), TPB>>>(pred_boxes, pred_scores,
                                                 pred_classes, gt_boxes,
                                                 gt_classes);
    ap_kernel<<<B, 256>>>(pred_scores, (float*)d_out);
}